// round 7
// baseline (speedup 1.0000x reference)
#include <cuda_runtime.h>
#include <math.h>

#define MTOK 50176
#define CCH 384
#define HWN 3136
#define PI_F 3.14159265358979323846f

// ---------------- scratch ----------------
__device__ float g_xt[(size_t)MTOK * CCH];
__device__ float g_xg[(size_t)MTOK * CCH];
__device__ float g_z [(size_t)MTOK * CCH];
__device__ float g_t1[(size_t)MTOK * CCH];
__device__ float g_u0[(size_t)MTOK * CCH];
__device__ float g_v0[(size_t)MTOK * CCH];
__device__ float g_cosb[(size_t)HWN * CCH];
__device__ float g_sinb[(size_t)HWN * CCH];
__device__ float g_D[56 * 56];

// ---------------- DCT matrix init ----------------
__global__ void dct_init_k(float* D) {
    int idx = blockIdx.x * 256 + threadIdx.x;
    if (idx < 56 * 56) {
        int k = idx / 56, n = idx % 56;
        double v = cos(3.14159265358979323846 * (2.0 * n + 1.0) * k / 112.0) * sqrt(2.0 / 56.0);
        if (k == 0) v *= (1.0 / sqrt(2.0));
        D[idx] = (float)v;
    }
}

// ---------------- depthwise 3x3 conv -> token-major ----------------
__global__ void dwconv_k(const float* __restrict__ x, const float* __restrict__ w,
                         const float* __restrict__ bias, float* __restrict__ xt) {
    __shared__ float s[8][33];
    int tx = threadIdx.x, ty = threadIdx.y;
    int wseg = blockIdx.x & 1;
    int h = blockIdx.x >> 1;
    int c = blockIdx.y * 8 + ty;
    int b = blockIdx.z;
    int ww = wseg * 32 + tx;

    if (ww < 56) {
        float acc = bias[c];
        const float* xp = x + ((size_t)(b * CCH + c) * 56) * 56;
        const float* wp = w + c * 9;
        #pragma unroll
        for (int kh = 0; kh < 3; kh++) {
            int hh = h + kh - 1;
            if (hh < 0 || hh >= 56) continue;
            #pragma unroll
            for (int kw = 0; kw < 3; kw++) {
                int wc = ww + kw - 1;
                if (wc < 0 || wc >= 56) continue;
                acc += xp[hh * 56 + wc] * wp[kh * 3 + kw];
            }
        }
        s[ty][tx] = acc;
    }
    __syncthreads();
    int tid = ty * 32 + tx;
    int wi = tid >> 3, ci = tid & 7;
    int wo = wseg * 32 + wi;
    if (wo < 56) {
        int cout = blockIdx.y * 8 + ci;
        size_t tok = (size_t)b * HWN + h * 56 + wo;
        xt[tok * CCH + cout] = s[ci][wi];
    }
}

// ---------------- TF32 tensor-core GEMM, 4 warps x (64x64), double-buffered ----------------
// Smem [row][16k] (64B row stride, conflict-free). K-permutation: thread qd
// consumes physical k {4qd..4qd+3}; A and B agree, so the sum is unchanged.
// EPI 0: +bias, split at n=384 -> O0 / O1 ; EPI 1: +bias -> O0 ; EPI 2: wave mod.
#define TBM 128
#define TBN 128
#define TBK 16

__device__ __forceinline__ unsigned f2tf32(float x) {
    unsigned r;
    asm("cvt.rna.tf32.f32 %0, %1;" : "=r"(r) : "f"(x));
    return r;
}

template <int EPI>
__global__ void __launch_bounds__(128, 2) gemm_tc(
    const float* __restrict__ A, const float* __restrict__ Wt,
    const float* __restrict__ bias,
    float* __restrict__ O0, float* __restrict__ O1,
    const float* __restrict__ U, const float* __restrict__ cosb,
    const float* __restrict__ sinb, const float* __restrict__ velb,
    const float* __restrict__ alphap,
    int M, int N, int K) {
    __shared__ unsigned As[2][TBM][TBK];
    __shared__ unsigned Bs[2][TBN][TBK];

    int tid = threadIdx.x;
    int lane = tid & 31;
    int warp = tid >> 5;          // 0..3
    int wm = warp & 1;            // 2 warps over M (64 each)
    int wn = warp >> 1;           // 2 warps over N (64 each)
    int m0 = blockIdx.y * TBM;
    int n0 = blockIdx.x * TBN;
    int grp = lane >> 2;          // 0..7
    int qd = lane & 3;            // 0..3
    int lr = tid >> 2;            // 0..31 (row base for loads)
    int lq = tid & 3;             // 0..3  (k quad)

    float acc[4][8][4];
    #pragma unroll
    for (int i = 0; i < 4; i++)
        #pragma unroll
        for (int j = 0; j < 8; j++)
            #pragma unroll
            for (int r = 0; r < 4; r++) acc[i][j][r] = 0.f;

    const float* Abase = A + (size_t)(m0 + lr) * K + lq * 4;
    const float* Bbase = Wt + (size_t)(n0 + lr) * K + lq * 4;
    size_t rowstr = (size_t)32 * K;

    float4 pa[4], pb[4];
    #pragma unroll
    for (int u = 0; u < 4; u++) {
        pa[u] = *(const float4*)(Abase + u * rowstr);
        pb[u] = *(const float4*)(Bbase + u * rowstr);
    }

    int stages = K / TBK;
    #pragma unroll
    for (int u = 0; u < 4; u++) {
        int r = lr + u * 32;
        As[0][r][lq * 4 + 0] = f2tf32(pa[u].x);
        As[0][r][lq * 4 + 1] = f2tf32(pa[u].y);
        As[0][r][lq * 4 + 2] = f2tf32(pa[u].z);
        As[0][r][lq * 4 + 3] = f2tf32(pa[u].w);
        Bs[0][r][lq * 4 + 0] = f2tf32(pb[u].x);
        Bs[0][r][lq * 4 + 1] = f2tf32(pb[u].y);
        Bs[0][r][lq * 4 + 2] = f2tf32(pb[u].z);
        Bs[0][r][lq * 4 + 3] = f2tf32(pb[u].w);
    }
    __syncthreads();

    for (int it = 0; it < stages; it++) {
        int s = it & 1;
        bool more = (it + 1 < stages);
        if (more) {
            int k0 = (it + 1) * TBK;
            #pragma unroll
            for (int u = 0; u < 4; u++) {
                pa[u] = *(const float4*)(Abase + k0 + u * rowstr);
                pb[u] = *(const float4*)(Bbase + k0 + u * rowstr);
            }
        }
        // A fragments: one LDS.128 per row-group covers both 8-wide k-chunks
        uint4 alo[4], ahi[4];
        #pragma unroll
        for (int mt = 0; mt < 4; mt++) {
            int mb = wm * 64 + mt * 16;
            alo[mt] = *(const uint4*)&As[s][mb + grp][qd * 4];
            ahi[mt] = *(const uint4*)&As[s][mb + grp + 8][qd * 4];
        }
        #pragma unroll
        for (int nt = 0; nt < 8; nt++) {
            int nb = wn * 64 + nt * 8;
            uint4 bv = *(const uint4*)&Bs[s][nb + grp][qd * 4];
            #pragma unroll
            for (int mt = 0; mt < 4; mt++) {
                asm volatile(
                    "mma.sync.aligned.m16n8k8.row.col.f32.tf32.tf32.f32 "
                    "{%0,%1,%2,%3}, {%4,%5,%6,%7}, {%8,%9}, {%0,%1,%2,%3};"
                    : "+f"(acc[mt][nt][0]), "+f"(acc[mt][nt][1]),
                      "+f"(acc[mt][nt][2]), "+f"(acc[mt][nt][3])
                    : "r"(alo[mt].x), "r"(ahi[mt].x), "r"(alo[mt].y), "r"(ahi[mt].y),
                      "r"(bv.x), "r"(bv.y));
                asm volatile(
                    "mma.sync.aligned.m16n8k8.row.col.f32.tf32.tf32.f32 "
                    "{%0,%1,%2,%3}, {%4,%5,%6,%7}, {%8,%9}, {%0,%1,%2,%3};"
                    : "+f"(acc[mt][nt][0]), "+f"(acc[mt][nt][1]),
                      "+f"(acc[mt][nt][2]), "+f"(acc[mt][nt][3])
                    : "r"(alo[mt].z), "r"(ahi[mt].z), "r"(alo[mt].w), "r"(ahi[mt].w),
                      "r"(bv.z), "r"(bv.w));
            }
        }
        if (more) {
            int d = s ^ 1;
            #pragma unroll
            for (int u = 0; u < 4; u++) {
                int r = lr + u * 32;
                As[d][r][lq * 4 + 0] = f2tf32(pa[u].x);
                As[d][r][lq * 4 + 1] = f2tf32(pa[u].y);
                As[d][r][lq * 4 + 2] = f2tf32(pa[u].z);
                As[d][r][lq * 4 + 3] = f2tf32(pa[u].w);
                Bs[d][r][lq * 4 + 0] = f2tf32(pb[u].x);
                Bs[d][r][lq * 4 + 1] = f2tf32(pb[u].y);
                Bs[d][r][lq * 4 + 2] = f2tf32(pb[u].z);
                Bs[d][r][lq * 4 + 3] = f2tf32(pb[u].w);
            }
        }
        __syncthreads();
    }

    float al = 0.f;
    if (EPI == 2) al = alphap[0];

    #pragma unroll
    for (int mt = 0; mt < 4; mt++) {
        int row0 = m0 + wm * 64 + mt * 16 + grp;
        #pragma unroll
        for (int nt = 0; nt < 8; nt++) {
            int col = n0 + wn * 64 + nt * 8 + qd * 2;
            float b0 = 0.f, b1 = 0.f;
            if (EPI == 0 || EPI == 1) { b0 = bias[col]; b1 = bias[col + 1]; }
            #pragma unroll
            for (int half = 0; half < 2; half++) {
                int row = row0 + half * 8;
                float v0 = acc[mt][nt][half * 2 + 0] + b0;
                float v1 = acc[mt][nt][half * 2 + 1] + b1;
                if (EPI == 0) {
                    if (col < 384)
                        *(float2*)&O0[(size_t)row * 384 + col] = make_float2(v0, v1);
                    else
                        *(float2*)&O1[(size_t)row * 384 + (col - 384)] = make_float2(v0, v1);
                } else if (EPI == 1) {
                    *(float2*)&O0[(size_t)row * N + col] = make_float2(v0, v1);
                } else {
                    int ij = row % HWN;
                    int i = ij / 56, j = ij % 56;
                    float wnv = PI_F * i / 56.f, wmv = PI_F * j / 56.f;
                    float decay = expf(-(wnv * wnv + wmv * wmv));
                    float2 uv = *(const float2*)&U[(size_t)row * 384 + col];
                    float ua = uv.x * decay, ub = uv.y * decay;
                    float va = v0, vb = v1;
                    if (ij == 0) { va += 56.f * velb[col]; vb += 56.f * velb[col + 1]; }
                    va *= decay; vb *= decay;
                    float2 cv = *(const float2*)&cosb[(size_t)ij * 384 + col];
                    float2 sv = *(const float2*)&sinb[(size_t)ij * 384 + col];
                    float fa = cv.x * ua + sv.x * (va + 0.5f * al * ua);
                    float fb = cv.y * ub + sv.y * (vb + 0.5f * al * ub);
                    *(float2*)&O0[(size_t)row * 384 + col] = make_float2(fa, fb);
                }
            }
        }
    }
}

// ---------------- fp32 FFMA GEMM for cos/sin table ----------------
#define BM 128
#define BN 64
#define BK 16

__global__ void __launch_bounds__(256) gemm_cs(
    const float* __restrict__ A, const float* __restrict__ Wt,
    const float* __restrict__ bias, const float* __restrict__ cptr,
    float* __restrict__ O0, float* __restrict__ O1,
    int M, int N, int K) {
    __shared__ float As[BK][BM + 4];
    __shared__ float Ws[BK][BN + 4];
    int tid = threadIdx.x;
    int m0 = blockIdx.y * BM;
    int n0 = blockIdx.x * BN;
    int mt = tid >> 4;
    int nt = tid & 15;

    float acc[8][4];
    #pragma unroll
    for (int i = 0; i < 8; i++)
        #pragma unroll
        for (int j = 0; j < 4; j++) acc[i][j] = 0.f;

    for (int k0 = 0; k0 < K; k0 += BK) {
        #pragma unroll
        for (int u = 0; u < 2; u++) {
            int f = tid + u * 256;
            int r = f >> 2, cq = f & 3;
            float4 v = make_float4(0.f, 0.f, 0.f, 0.f);
            if (m0 + r < M)
                v = *(const float4*)(A + (size_t)(m0 + r) * K + k0 + cq * 4);
            As[cq * 4 + 0][r] = v.x; As[cq * 4 + 1][r] = v.y;
            As[cq * 4 + 2][r] = v.z; As[cq * 4 + 3][r] = v.w;
        }
        {
            int r = tid >> 2, cq = tid & 3;
            float4 v = *(const float4*)(Wt + (size_t)(n0 + r) * K + k0 + cq * 4);
            Ws[cq * 4 + 0][r] = v.x; Ws[cq * 4 + 1][r] = v.y;
            Ws[cq * 4 + 2][r] = v.z; Ws[cq * 4 + 3][r] = v.w;
        }
        __syncthreads();
        #pragma unroll
        for (int kk = 0; kk < BK; kk++) {
            float4 a0 = *(const float4*)&As[kk][mt * 8];
            float4 a1 = *(const float4*)&As[kk][mt * 8 + 4];
            float4 bv = *(const float4*)&Ws[kk][nt * 4];
            float av[8] = {a0.x, a0.y, a0.z, a0.w, a1.x, a1.y, a1.z, a1.w};
            float bvv[4] = {bv.x, bv.y, bv.z, bv.w};
            #pragma unroll
            for (int i = 0; i < 8; i++)
                #pragma unroll
                for (int j = 0; j < 4; j++) acc[i][j] += av[i] * bvv[j];
        }
        __syncthreads();
    }

    float cc = cptr[0], ic = 1.f / (cc + 1e-6f);

    #pragma unroll
    for (int i = 0; i < 8; i++) {
        int m = m0 + mt * 8 + i;
        if (m >= M) continue;
        #pragma unroll
        for (int j = 0; j < 4; j++) {
            int n = n0 + nt * 4 + j;
            float v = acc[i][j] + bias[n];
            v = fmaxf(v, 0.f);
            float a = cc * v;
            O0[(size_t)m * N + n] = cosf(a);
            O1[(size_t)m * N + n] = sinf(a) * ic;
        }
    }
}

// ---------------- batched DCT stage, 2 groups per block ----------------
__global__ void __launch_bounds__(256) dct2_k(const float* __restrict__ Dm, int transD,
                                              const float* __restrict__ X,
                                              float* __restrict__ O, int N) {
    extern __shared__ float sm[];
    float* Ds = sm;                       // 56*57
    float* Xs = sm + 56 * 57;             // 2*56*128
    int tid = threadIdx.x;
    int g0 = blockIdx.y * 2;
    int n0 = blockIdx.x * 128;

    for (int f = tid; f < 56 * 56; f += 256) {
        int i = f / 56, k = f % 56;
        Ds[i * 57 + k] = transD ? Dm[k * 56 + i] : Dm[i * 56 + k];
    }
    #pragma unroll
    for (int gg = 0; gg < 2; gg++) {
        const float* Xg = X + (size_t)(g0 + gg) * 56 * N + n0;
        float* Xd = Xs + gg * 56 * 128;
        for (int f = tid; f < 56 * 128; f += 256) {
            int h = f >> 7, n = f & 127;
            Xd[h * 128 + n] = Xg[(size_t)h * N + n];
        }
    }
    __syncthreads();

    int ty = tid >> 5, tx = tid & 31;
    float acc[2][7][4];
    #pragma unroll
    for (int gg = 0; gg < 2; gg++)
        #pragma unroll
        for (int ii = 0; ii < 7; ii++)
            #pragma unroll
            for (int j = 0; j < 4; j++) acc[gg][ii][j] = 0.f;

    for (int k = 0; k < 56; k++) {
        float4 b0 = *(const float4*)&Xs[k * 128 + tx * 4];
        float4 b1 = *(const float4*)&Xs[56 * 128 + k * 128 + tx * 4];
        #pragma unroll
        for (int ii = 0; ii < 7; ii++) {
            float a = Ds[(ty * 7 + ii) * 57 + k];
            acc[0][ii][0] += a * b0.x; acc[0][ii][1] += a * b0.y;
            acc[0][ii][2] += a * b0.z; acc[0][ii][3] += a * b0.w;
            acc[1][ii][0] += a * b1.x; acc[1][ii][1] += a * b1.y;
            acc[1][ii][2] += a * b1.z; acc[1][ii][3] += a * b1.w;
        }
    }
    #pragma unroll
    for (int gg = 0; gg < 2; gg++) {
        float* Og = O + (size_t)(g0 + gg) * 56 * N + n0;
        #pragma unroll
        for (int ii = 0; ii < 7; ii++) {
            int i = ty * 7 + ii;
            *(float4*)&Og[(size_t)i * N + tx * 4] =
                make_float4(acc[gg][ii][0], acc[gg][ii][1], acc[gg][ii][2], acc[gg][ii][3]);
        }
    }
}

// ---------------- LayerNorm + SiLU gate ----------------
__global__ void ln_gate_k(const float* __restrict__ y, const float* __restrict__ z,
                          const float* __restrict__ g, const float* __restrict__ b,
                          float* __restrict__ out) {
    int warp = threadIdx.x >> 5, lane = threadIdx.x & 31;
    size_t m = (size_t)blockIdx.x * 8 + warp;
    const float* yr = y + m * CCH;
    float vals[12];
    float s = 0.f;
    #pragma unroll
    for (int t = 0; t < 12; t++) { vals[t] = yr[lane + t * 32]; s += vals[t]; }
    #pragma unroll
    for (int o = 16; o > 0; o >>= 1) s += __shfl_xor_sync(0xffffffff, s, o);
    float mu = s * (1.f / 384.f);
    float q = 0.f;
    #pragma unroll
    for (int t = 0; t < 12; t++) { float d = vals[t] - mu; q += d * d; }
    #pragma unroll
    for (int o = 16; o > 0; o >>= 1) q += __shfl_xor_sync(0xffffffff, q, o);
    float rstd = rsqrtf(q * (1.f / 384.f) + 1e-5f);
    #pragma unroll
    for (int t = 0; t < 12; t++) {
        int c = lane + t * 32;
        float yn = (vals[t] - mu) * rstd * g[c] + b[c];
        float zz = z[m * CCH + c];
        out[m * CCH + c] = yn * (zz / (1.f + expf(-zz)));
    }
}

// ---------------- [B,HW,C] -> [B,C,HW] transpose ----------------
__global__ void transpose_k(const float* __restrict__ in, float* __restrict__ out) {
    __shared__ float s[32][33];
    int tx = threadIdx.x, ty = threadIdx.y;
    int hw0 = blockIdx.x * 32;
    int c0 = blockIdx.y * 32;
    int b = blockIdx.z;
    #pragma unroll
    for (int r = 0; r < 4; r++) {
        int hw = hw0 + ty + r * 8;
        s[ty + r * 8][tx] = in[((size_t)b * HWN + hw) * CCH + c0 + tx];
    }
    __syncthreads();
    #pragma unroll
    for (int r = 0; r < 4; r++) {
        int c = c0 + ty + r * 8;
        out[((size_t)b * CCH + c) * HWN + hw0 + tx] = s[tx][ty + r * 8];
    }
}

// ---------------- launch ----------------
extern "C" void kernel_launch(void* const* d_in, const int* in_sizes, int n_in,
                              void* d_out, int out_size) {
    const float* x          = (const float*)d_in[0];
    const float* freq_embed = (const float*)d_in[1];
    const float* dw_w       = (const float*)d_in[2];
    const float* dw_b       = (const float*)d_in[3];
    const float* lin_w      = (const float*)d_in[4];
    const float* lin_b      = (const float*)d_in[5];
    const float* vel_w      = (const float*)d_in[6];
    const float* vel_b      = (const float*)d_in[7];
    const float* tok_w      = (const float*)d_in[8];
    const float* tok_b      = (const float*)d_in[9];
    const float* ln_g       = (const float*)d_in[10];
    const float* ln_b       = (const float*)d_in[11];
    const float* out_w      = (const float*)d_in[12];
    const float* out_b      = (const float*)d_in[13];
    const float* cptr       = (const float*)d_in[14];
    const float* alphap     = (const float*)d_in[15];
    float* outp = (float*)d_out;

    float *xt, *xg, *z, *t1, *u0, *v0, *cb, *sb, *Dm;
    cudaGetSymbolAddress((void**)&xt, g_xt);
    cudaGetSymbolAddress((void**)&xg, g_xg);
    cudaGetSymbolAddress((void**)&z,  g_z);
    cudaGetSymbolAddress((void**)&t1, g_t1);
    cudaGetSymbolAddress((void**)&u0, g_u0);
    cudaGetSymbolAddress((void**)&v0, g_v0);
    cudaGetSymbolAddress((void**)&cb, g_cosb);
    cudaGetSymbolAddress((void**)&sb, g_sinb);
    cudaGetSymbolAddress((void**)&Dm, g_D);

    const int dctSmem = (56 * 57 + 2 * 56 * 128) * 4;   // 70112 B
    cudaFuncSetAttribute(dct2_k, cudaFuncAttributeMaxDynamicSharedMemorySize, dctSmem);

    dct_init_k<<<13, 256>>>(Dm);

    // depthwise conv -> token-major xt
    dwconv_k<<<dim3(112, 48, 16), dim3(32, 8)>>>(x, dw_w, dw_b, xt);

    // cos/sin tables (independent; fp32 for precision)
    gemm_cs<<<dim3(384 / BN, (HWN + BM - 1) / BM), 256>>>(freq_embed, tok_w, tok_b, cptr,
                                                          cb, sb, HWN, 384, 384);

    // xz = xt @ lin_w.T + lin_b ; split -> xg, z
    gemm_tc<0><<<dim3(768 / TBN, MTOK / TBM), 128>>>(xt, lin_w, lin_b, xg, z,
                                                     nullptr, nullptr, nullptr, nullptr, nullptr,
                                                     MTOK, 768, 384);

    // u0 = DCT2(xg)
    dct2_k<<<dim3(168, 8), 256, dctSmem>>>(Dm, 0, xg, t1, 21504);
    dct2_k<<<dim3(3, 448), 256, dctSmem>>>(Dm, 0, t1, u0, 384);

    // fin = mod(u0, u0 @ vel_w.T) -> t1   (mod fused into epilogue)
    gemm_tc<2><<<dim3(384 / TBN, MTOK / TBM), 128>>>(u0, vel_w, nullptr, t1, nullptr,
                                                     u0, cb, sb, vel_b, alphap,
                                                     MTOK, 384, 384);

    // y = IDCT2(fin) -> u0
    dct2_k<<<dim3(168, 8), 256, dctSmem>>>(Dm, 1, t1, xg, 21504);
    dct2_k<<<dim3(3, 448), 256, dctSmem>>>(Dm, 1, xg, u0, 384);

    // LayerNorm + SiLU(z) gate -> v0
    ln_gate_k<<<MTOK / 8, 256>>>(u0, z, ln_g, ln_b, v0);

    // out = gated @ out_w.T + out_b -> t1, then transpose to NCHW
    gemm_tc<1><<<dim3(384 / TBN, MTOK / TBM), 128>>>(v0, out_w, out_b, t1, nullptr,
                                                     nullptr, nullptr, nullptr, nullptr, nullptr,
                                                     MTOK, 384, 384);
    transpose_k<<<dim3(98, 12, 16), dim3(32, 8)>>>(t1, outp);
}

// round 8
// speedup vs baseline: 1.0326x; 1.0326x over previous
#include <cuda_runtime.h>
#include <math.h>
#include <stdint.h>

#define MTOK 50176
#define CCH 384
#define HWN 3136
#define PI_F 3.14159265358979323846f

// ---------------- scratch ----------------
__device__ float g_xt[(size_t)MTOK * CCH];
__device__ float g_xg[(size_t)MTOK * CCH];
__device__ float g_z [(size_t)MTOK * CCH];
__device__ float g_t1[(size_t)MTOK * CCH];
__device__ float g_u0[(size_t)MTOK * CCH];
__device__ float g_v0[(size_t)MTOK * CCH];
__device__ float g_cosb[(size_t)HWN * CCH];
__device__ float g_sinb[(size_t)HWN * CCH];
__device__ float g_D[56 * 56];
__device__ float g_wl[768 * 384];
__device__ float g_wv[384 * 384];
__device__ float g_wo[384 * 384];

__device__ __forceinline__ unsigned f2tf32(float x) {
    unsigned r;
    asm("cvt.rna.tf32.f32 %0, %1;" : "=r"(r) : "f"(x));
    return r;
}
__device__ __forceinline__ float round_tf32(float x) {
    return __uint_as_float(f2tf32(x));
}
__device__ __forceinline__ uint32_t smem_u32(const void* p) {
    uint32_t a;
    asm("{ .reg .u64 t; cvta.to.shared.u64 t, %1; cvt.u32.u64 %0, t; }" : "=r"(a) : "l"(p));
    return a;
}
#define CP16(smaddr, gptr) \
    asm volatile("cp.async.ca.shared.global [%0], [%1], 16;" :: "r"(smaddr), "l"(gptr))

// ---------------- weight pre-round ----------------
__global__ void cvtw_k(const float* __restrict__ in, float* __restrict__ out, int n) {
    int i = blockIdx.x * 256 + threadIdx.x;
    if (i < n) out[i] = round_tf32(in[i]);
}

// ---------------- DCT matrix init ----------------
__global__ void dct_init_k(float* D) {
    int idx = blockIdx.x * 256 + threadIdx.x;
    if (idx < 56 * 56) {
        int k = idx / 56, n = idx % 56;
        double v = cos(3.14159265358979323846 * (2.0 * n + 1.0) * k / 112.0) * sqrt(2.0 / 56.0);
        if (k == 0) v *= (1.0 / sqrt(2.0));
        D[idx] = (float)v;
    }
}

// ---------------- depthwise 3x3 conv -> token-major (tf32-rounded output) ----------------
__global__ void dwconv_k(const float* __restrict__ x, const float* __restrict__ w,
                         const float* __restrict__ bias, float* __restrict__ xt) {
    __shared__ float s[8][33];
    int tx = threadIdx.x, ty = threadIdx.y;
    int wseg = blockIdx.x & 1;
    int h = blockIdx.x >> 1;
    int c = blockIdx.y * 8 + ty;
    int b = blockIdx.z;
    int ww = wseg * 32 + tx;

    if (ww < 56) {
        float acc = bias[c];
        const float* xp = x + ((size_t)(b * CCH + c) * 56) * 56;
        const float* wp = w + c * 9;
        #pragma unroll
        for (int kh = 0; kh < 3; kh++) {
            int hh = h + kh - 1;
            if (hh < 0 || hh >= 56) continue;
            #pragma unroll
            for (int kw = 0; kw < 3; kw++) {
                int wc = ww + kw - 1;
                if (wc < 0 || wc >= 56) continue;
                acc += xp[hh * 56 + wc] * wp[kh * 3 + kw];
            }
        }
        s[ty][tx] = acc;
    }
    __syncthreads();
    int tid = ty * 32 + tx;
    int wi = tid >> 3, ci = tid & 7;
    int wo = wseg * 32 + wi;
    if (wo < 56) {
        int cout = blockIdx.y * 8 + ci;
        size_t tok = (size_t)b * HWN + h * 56 + wo;
        xt[tok * CCH + cout] = round_tf32(s[ci][wi]);
    }
}

// ---------------- TF32 TC GEMM: 8 warps x (64x32), cp.async 3-stage, no cvt ----------------
// Operands must be pre-rounded to tf32. Smem [row][16k]. K-permutation: thread qd
// consumes physical k {4qd..4qd+3} for both A and B -> sum unchanged.
// EPI 0: +bias, split at n=384 -> O0/O1 ; EPI 1: +bias -> O0 ; EPI 2: wave mod.
#define TBM 128
#define TBN 128
#define TBK 16
#define NST 3

template <int EPI>
__global__ void __launch_bounds__(256, 2) gemm_tc(
    const float* __restrict__ A, const float* __restrict__ Wt,
    const float* __restrict__ bias,
    float* __restrict__ O0, float* __restrict__ O1,
    const float* __restrict__ U, const float* __restrict__ cosb,
    const float* __restrict__ sinb, const float* __restrict__ velb,
    const float* __restrict__ alphap,
    int M, int N, int K) {
    __shared__ unsigned As[NST][TBM][TBK];
    __shared__ unsigned Bs[NST][TBN][TBK];

    int tid = threadIdx.x;
    int lane = tid & 31;
    int warp = tid >> 5;
    int wm = warp & 1;        // 2 warps over M (64 each)
    int wn = warp >> 1;       // 4 warps over N (32 each)
    int m0 = blockIdx.y * TBM;
    int n0 = blockIdx.x * TBN;
    int grp = lane >> 2;
    int qd = lane & 3;

    float acc[4][4][4];
    #pragma unroll
    for (int i = 0; i < 4; i++)
        #pragma unroll
        for (int j = 0; j < 4; j++)
            #pragma unroll
            for (int r = 0; r < 4; r++) acc[i][j][r] = 0.f;

    // cp.async mapping: 512 chunks of 16B per matrix per stage; thread does 2 each
    int row0 = tid >> 2;          // 0..63
    int seg  = tid & 3;           // 0..3
    const float* ga0 = A + (size_t)(m0 + row0) * K + seg * 4;
    const float* ga1 = A + (size_t)(m0 + row0 + 64) * K + seg * 4;
    const float* gb0 = Wt + (size_t)(n0 + row0) * K + seg * 4;
    const float* gb1 = Wt + (size_t)(n0 + row0 + 64) * K + seg * 4;
    uint32_t asb = smem_u32(&As[0][0][0]) + row0 * 64 + seg * 16;
    uint32_t bsb = smem_u32(&Bs[0][0][0]) + row0 * 64 + seg * 16;

    int stages = K / TBK;     // 24

    #pragma unroll
    for (int p = 0; p < 2; p++) {
        int k0 = p * TBK;
        uint32_t sa = asb + p * 8192;
        uint32_t sbm = bsb + p * 8192;
        CP16(sa, ga0 + k0);
        CP16(sa + 64 * 64, ga1 + k0);
        CP16(sbm, gb0 + k0);
        CP16(sbm + 64 * 64, gb1 + k0);
        asm volatile("cp.async.commit_group;");
    }

    for (int it = 0; it < stages; it++) {
        if (it + 2 < stages) {
            asm volatile("cp.async.wait_group 1;");
        } else {
            asm volatile("cp.async.wait_group 0;");
        }
        __syncthreads();
        if (it + 2 < stages) {
            int s = (it + 2) % NST;
            int k0 = (it + 2) * TBK;
            uint32_t sa = asb + s * 8192;
            uint32_t sbm = bsb + s * 8192;
            CP16(sa, ga0 + k0);
            CP16(sa + 64 * 64, ga1 + k0);
            CP16(sbm, gb0 + k0);
            CP16(sbm + 64 * 64, gb1 + k0);
            asm volatile("cp.async.commit_group;");
        }

        int s = it % NST;
        uint4 alo[4], ahi[4];
        #pragma unroll
        for (int mt = 0; mt < 4; mt++) {
            int mb = wm * 64 + mt * 16;
            alo[mt] = *(const uint4*)&As[s][mb + grp][qd * 4];
            ahi[mt] = *(const uint4*)&As[s][mb + grp + 8][qd * 4];
        }
        #pragma unroll
        for (int nt = 0; nt < 4; nt++) {
            int nb = wn * 32 + nt * 8;
            uint4 bv = *(const uint4*)&Bs[s][nb + grp][qd * 4];
            #pragma unroll
            for (int mt = 0; mt < 4; mt++) {
                asm volatile(
                    "mma.sync.aligned.m16n8k8.row.col.f32.tf32.tf32.f32 "
                    "{%0,%1,%2,%3}, {%4,%5,%6,%7}, {%8,%9}, {%0,%1,%2,%3};"
                    : "+f"(acc[mt][nt][0]), "+f"(acc[mt][nt][1]),
                      "+f"(acc[mt][nt][2]), "+f"(acc[mt][nt][3])
                    : "r"(alo[mt].x), "r"(ahi[mt].x), "r"(alo[mt].y), "r"(ahi[mt].y),
                      "r"(bv.x), "r"(bv.y));
                asm volatile(
                    "mma.sync.aligned.m16n8k8.row.col.f32.tf32.tf32.f32 "
                    "{%0,%1,%2,%3}, {%4,%5,%6,%7}, {%8,%9}, {%0,%1,%2,%3};"
                    : "+f"(acc[mt][nt][0]), "+f"(acc[mt][nt][1]),
                      "+f"(acc[mt][nt][2]), "+f"(acc[mt][nt][3])
                    : "r"(alo[mt].z), "r"(ahi[mt].z), "r"(alo[mt].w), "r"(ahi[mt].w),
                      "r"(bv.z), "r"(bv.w));
            }
        }
        __syncthreads();
    }

    float al = 0.f;
    if (EPI == 2) al = alphap[0];

    #pragma unroll
    for (int mt = 0; mt < 4; mt++) {
        int row0e = m0 + wm * 64 + mt * 16 + grp;
        #pragma unroll
        for (int nt = 0; nt < 4; nt++) {
            int col = n0 + wn * 32 + nt * 8 + qd * 2;
            float b0 = 0.f, b1 = 0.f;
            if (EPI == 0 || EPI == 1) { b0 = bias[col]; b1 = bias[col + 1]; }
            #pragma unroll
            for (int half = 0; half < 2; half++) {
                int row = row0e + half * 8;
                float v0 = acc[mt][nt][half * 2 + 0] + b0;
                float v1 = acc[mt][nt][half * 2 + 1] + b1;
                if (EPI == 0) {
                    if (col < 384)
                        *(float2*)&O0[(size_t)row * 384 + col] = make_float2(v0, v1);
                    else
                        *(float2*)&O1[(size_t)row * 384 + (col - 384)] = make_float2(v0, v1);
                } else if (EPI == 1) {
                    *(float2*)&O0[(size_t)row * N + col] = make_float2(v0, v1);
                } else {
                    int ij = row % HWN;
                    int i = ij / 56, j = ij % 56;
                    float wnv = PI_F * i / 56.f, wmv = PI_F * j / 56.f;
                    float decay = expf(-(wnv * wnv + wmv * wmv));
                    float2 uv = *(const float2*)&U[(size_t)row * 384 + col];
                    float ua = uv.x * decay, ub = uv.y * decay;
                    float va = v0, vb = v1;
                    if (ij == 0) { va += 56.f * velb[col]; vb += 56.f * velb[col + 1]; }
                    va *= decay; vb *= decay;
                    float2 cv = *(const float2*)&cosb[(size_t)ij * 384 + col];
                    float2 sv = *(const float2*)&sinb[(size_t)ij * 384 + col];
                    float fa = cv.x * ua + sv.x * (va + 0.5f * al * ua);
                    float fb = cv.y * ub + sv.y * (vb + 0.5f * al * ub);
                    *(float2*)&O0[(size_t)row * 384 + col] = make_float2(fa, fb);
                }
            }
        }
    }
}

// ---------------- fp32 FFMA GEMM for cos/sin table ----------------
#define BM 128
#define BN 64
#define BK 16

__global__ void __launch_bounds__(256) gemm_cs(
    const float* __restrict__ A, const float* __restrict__ Wt,
    const float* __restrict__ bias, const float* __restrict__ cptr,
    float* __restrict__ O0, float* __restrict__ O1,
    int M, int N, int K) {
    __shared__ float As[BK][BM + 4];
    __shared__ float Ws[BK][BN + 4];
    int tid = threadIdx.x;
    int m0 = blockIdx.y * BM;
    int n0 = blockIdx.x * BN;
    int mt = tid >> 4;
    int nt = tid & 15;

    float acc[8][4];
    #pragma unroll
    for (int i = 0; i < 8; i++)
        #pragma unroll
        for (int j = 0; j < 4; j++) acc[i][j] = 0.f;

    for (int k0 = 0; k0 < K; k0 += BK) {
        #pragma unroll
        for (int u = 0; u < 2; u++) {
            int f = tid + u * 256;
            int r = f >> 2, cq = f & 3;
            float4 v = make_float4(0.f, 0.f, 0.f, 0.f);
            if (m0 + r < M)
                v = *(const float4*)(A + (size_t)(m0 + r) * K + k0 + cq * 4);
            As[cq * 4 + 0][r] = v.x; As[cq * 4 + 1][r] = v.y;
            As[cq * 4 + 2][r] = v.z; As[cq * 4 + 3][r] = v.w;
        }
        {
            int r = tid >> 2, cq = tid & 3;
            float4 v = *(const float4*)(Wt + (size_t)(n0 + r) * K + k0 + cq * 4);
            Ws[cq * 4 + 0][r] = v.x; Ws[cq * 4 + 1][r] = v.y;
            Ws[cq * 4 + 2][r] = v.z; Ws[cq * 4 + 3][r] = v.w;
        }
        __syncthreads();
        #pragma unroll
        for (int kk = 0; kk < BK; kk++) {
            float4 a0 = *(const float4*)&As[kk][mt * 8];
            float4 a1 = *(const float4*)&As[kk][mt * 8 + 4];
            float4 bv = *(const float4*)&Ws[kk][nt * 4];
            float av[8] = {a0.x, a0.y, a0.z, a0.w, a1.x, a1.y, a1.z, a1.w};
            float bvv[4] = {bv.x, bv.y, bv.z, bv.w};
            #pragma unroll
            for (int i = 0; i < 8; i++)
                #pragma unroll
                for (int j = 0; j < 4; j++) acc[i][j] += av[i] * bvv[j];
        }
        __syncthreads();
    }

    float cc = cptr[0], ic = 1.f / (cc + 1e-6f);

    #pragma unroll
    for (int i = 0; i < 8; i++) {
        int m = m0 + mt * 8 + i;
        if (m >= M) continue;
        #pragma unroll
        for (int j = 0; j < 4; j++) {
            int n = n0 + nt * 4 + j;
            float v = acc[i][j] + bias[n];
            v = fmaxf(v, 0.f);
            float a = cc * v;
            O0[(size_t)m * N + n] = cosf(a);
            O1[(size_t)m * N + n] = sinf(a) * ic;
        }
    }
}

// ---------------- batched DCT stage, 2 groups per block ----------------
// ROUND=1: tf32-round the output (when it feeds a tensor-core GEMM).
template <int ROUND>
__global__ void __launch_bounds__(256) dct2_k(const float* __restrict__ Dm, int transD,
                                              const float* __restrict__ X,
                                              float* __restrict__ O, int N) {
    extern __shared__ float sm[];
    float* Ds = sm;                       // 56*57
    float* Xs = sm + 56 * 57;             // 2*56*128
    int tid = threadIdx.x;
    int g0 = blockIdx.y * 2;
    int n0 = blockIdx.x * 128;

    for (int f = tid; f < 56 * 56; f += 256) {
        int i = f / 56, k = f % 56;
        Ds[i * 57 + k] = transD ? Dm[k * 56 + i] : Dm[i * 56 + k];
    }
    #pragma unroll
    for (int gg = 0; gg < 2; gg++) {
        const float* Xg = X + (size_t)(g0 + gg) * 56 * N + n0;
        float* Xd = Xs + gg * 56 * 128;
        for (int f = tid; f < 56 * 128; f += 256) {
            int h = f >> 7, n = f & 127;
            Xd[h * 128 + n] = Xg[(size_t)h * N + n];
        }
    }
    __syncthreads();

    int ty = tid >> 5, tx = tid & 31;
    float acc[2][7][4];
    #pragma unroll
    for (int gg = 0; gg < 2; gg++)
        #pragma unroll
        for (int ii = 0; ii < 7; ii++)
            #pragma unroll
            for (int j = 0; j < 4; j++) acc[gg][ii][j] = 0.f;

    for (int k = 0; k < 56; k++) {
        float4 b0 = *(const float4*)&Xs[k * 128 + tx * 4];
        float4 b1 = *(const float4*)&Xs[56 * 128 + k * 128 + tx * 4];
        #pragma unroll
        for (int ii = 0; ii < 7; ii++) {
            float a = Ds[(ty * 7 + ii) * 57 + k];
            acc[0][ii][0] += a * b0.x; acc[0][ii][1] += a * b0.y;
            acc[0][ii][2] += a * b0.z; acc[0][ii][3] += a * b0.w;
            acc[1][ii][0] += a * b1.x; acc[1][ii][1] += a * b1.y;
            acc[1][ii][2] += a * b1.z; acc[1][ii][3] += a * b1.w;
        }
    }
    #pragma unroll
    for (int gg = 0; gg < 2; gg++) {
        float* Og = O + (size_t)(g0 + gg) * 56 * N + n0;
        #pragma unroll
        for (int ii = 0; ii < 7; ii++) {
            int i = ty * 7 + ii;
            float4 o = make_float4(acc[gg][ii][0], acc[gg][ii][1], acc[gg][ii][2], acc[gg][ii][3]);
            if (ROUND) {
                o.x = round_tf32(o.x); o.y = round_tf32(o.y);
                o.z = round_tf32(o.z); o.w = round_tf32(o.w);
            }
            *(float4*)&Og[(size_t)i * N + tx * 4] = o;
        }
    }
}

// ---------------- LayerNorm + SiLU gate (tf32-rounded output) ----------------
__global__ void ln_gate_k(const float* __restrict__ y, const float* __restrict__ z,
                          const float* __restrict__ g, const float* __restrict__ b,
                          float* __restrict__ out) {
    int warp = threadIdx.x >> 5, lane = threadIdx.x & 31;
    size_t m = (size_t)blockIdx.x * 8 + warp;
    const float* yr = y + m * CCH;
    float vals[12];
    float s = 0.f;
    #pragma unroll
    for (int t = 0; t < 12; t++) { vals[t] = yr[lane + t * 32]; s += vals[t]; }
    #pragma unroll
    for (int o = 16; o > 0; o >>= 1) s += __shfl_xor_sync(0xffffffff, s, o);
    float mu = s * (1.f / 384.f);
    float q = 0.f;
    #pragma unroll
    for (int t = 0; t < 12; t++) { float d = vals[t] - mu; q += d * d; }
    #pragma unroll
    for (int o = 16; o > 0; o >>= 1) q += __shfl_xor_sync(0xffffffff, q, o);
    float rstd = rsqrtf(q * (1.f / 384.f) + 1e-5f);
    #pragma unroll
    for (int t = 0; t < 12; t++) {
        int c = lane + t * 32;
        float yn = (vals[t] - mu) * rstd * g[c] + b[c];
        float zz = z[m * CCH + c];
        out[m * CCH + c] = round_tf32(yn * (zz / (1.f + expf(-zz))));
    }
}

// ---------------- [B,HW,C] -> [B,C,HW] transpose ----------------
__global__ void transpose_k(const float* __restrict__ in, float* __restrict__ out) {
    __shared__ float s[32][33];
    int tx = threadIdx.x, ty = threadIdx.y;
    int hw0 = blockIdx.x * 32;
    int c0 = blockIdx.y * 32;
    int b = blockIdx.z;
    #pragma unroll
    for (int r = 0; r < 4; r++) {
        int hw = hw0 + ty + r * 8;
        s[ty + r * 8][tx] = in[((size_t)b * HWN + hw) * CCH + c0 + tx];
    }
    __syncthreads();
    #pragma unroll
    for (int r = 0; r < 4; r++) {
        int c = c0 + ty + r * 8;
        out[((size_t)b * CCH + c) * HWN + hw0 + tx] = s[tx][ty + r * 8];
    }
}

// ---------------- launch ----------------
extern "C" void kernel_launch(void* const* d_in, const int* in_sizes, int n_in,
                              void* d_out, int out_size) {
    const float* x          = (const float*)d_in[0];
    const float* freq_embed = (const float*)d_in[1];
    const float* dw_w       = (const float*)d_in[2];
    const float* dw_b       = (const float*)d_in[3];
    const float* lin_w      = (const float*)d_in[4];
    const float* lin_b      = (const float*)d_in[5];
    const float* vel_w      = (const float*)d_in[6];
    const float* vel_b      = (const float*)d_in[7];
    const float* tok_w      = (const float*)d_in[8];
    const float* tok_b      = (const float*)d_in[9];
    const float* ln_g       = (const float*)d_in[10];
    const float* ln_b       = (const float*)d_in[11];
    const float* out_w      = (const float*)d_in[12];
    const float* out_b      = (const float*)d_in[13];
    const float* cptr       = (const float*)d_in[14];
    const float* alphap     = (const float*)d_in[15];
    float* outp = (float*)d_out;

    float *xt, *xg, *z, *t1, *u0, *v0, *cb, *sb, *Dm, *wl, *wv, *wo;
    cudaGetSymbolAddress((void**)&xt, g_xt);
    cudaGetSymbolAddress((void**)&xg, g_xg);
    cudaGetSymbolAddress((void**)&z,  g_z);
    cudaGetSymbolAddress((void**)&t1, g_t1);
    cudaGetSymbolAddress((void**)&u0, g_u0);
    cudaGetSymbolAddress((void**)&v0, g_v0);
    cudaGetSymbolAddress((void**)&cb, g_cosb);
    cudaGetSymbolAddress((void**)&sb, g_sinb);
    cudaGetSymbolAddress((void**)&Dm, g_D);
    cudaGetSymbolAddress((void**)&wl, g_wl);
    cudaGetSymbolAddress((void**)&wv, g_wv);
    cudaGetSymbolAddress((void**)&wo, g_wo);

    const int dctSmem = (56 * 57 + 2 * 56 * 128) * 4;   // 70112 B
    cudaFuncSetAttribute(dct2_k<0>, cudaFuncAttributeMaxDynamicSharedMemorySize, dctSmem);
    cudaFuncSetAttribute(dct2_k<1>, cudaFuncAttributeMaxDynamicSharedMemorySize, dctSmem);

    dct_init_k<<<13, 256>>>(Dm);
    cvtw_k<<<(768 * 384 + 255) / 256, 256>>>(lin_w, wl, 768 * 384);
    cvtw_k<<<(384 * 384 + 255) / 256, 256>>>(vel_w, wv, 384 * 384);
    cvtw_k<<<(384 * 384 + 255) / 256, 256>>>(out_w, wo, 384 * 384);

    // depthwise conv -> token-major xt (tf32-rounded)
    dwconv_k<<<dim3(112, 48, 16), dim3(32, 8)>>>(x, dw_w, dw_b, xt);

    // cos/sin tables (fp32 for precision)
    gemm_cs<<<dim3(384 / BN, (HWN + BM - 1) / BM), 256>>>(freq_embed, tok_w, tok_b, cptr,
                                                          cb, sb, HWN, 384, 384);

    // xz = xt @ lin_w.T + lin_b ; split -> xg, z
    gemm_tc<0><<<dim3(768 / TBN, MTOK / TBM), 256>>>(xt, wl, lin_b, xg, z,
                                                     nullptr, nullptr, nullptr, nullptr, nullptr,
                                                     MTOK, 768, 384);

    // u0 = DCT2(xg): stage1 full precision, stage2 rounded (feeds gemm<2>)
    dct2_k<0><<<dim3(168, 8), 256, dctSmem>>>(Dm, 0, xg, t1, 21504);
    dct2_k<1><<<dim3(3, 448), 256, dctSmem>>>(Dm, 0, t1, u0, 384);

    // fin = mod(u0, u0 @ vel_w.T) -> t1   (mod fused into epilogue)
    gemm_tc<2><<<dim3(384 / TBN, MTOK / TBM), 256>>>(u0, wv, nullptr, t1, nullptr,
                                                     u0, cb, sb, vel_b, alphap,
                                                     MTOK, 384, 384);

    // y = IDCT2(fin) -> u0  (full precision; feeds ln_gate, not a TC GEMM)
    dct2_k<0><<<dim3(168, 8), 256, dctSmem>>>(Dm, 1, t1, xg, 21504);
    dct2_k<0><<<dim3(3, 448), 256, dctSmem>>>(Dm, 1, xg, u0, 384);

    // LayerNorm + SiLU(z) gate -> v0 (tf32-rounded)
    ln_gate_k<<<MTOK / 8, 256>>>(u0, z, ln_g, ln_b, v0);

    // out = gated @ out_w.T + out_b -> t1, then transpose to NCHW
    gemm_tc<1><<<dim3(384 / TBN, MTOK / TBM), 256>>>(v0, wo, out_b, t1, nullptr,
                                                     nullptr, nullptr, nullptr, nullptr, nullptr,
                                                     MTOK, 384, 384);
    transpose_k<<<dim3(98, 12, 16), dim3(32, 8)>>>(t1, outp);
}

// round 9
// speedup vs baseline: 1.1337x; 1.0980x over previous
#include <cuda_runtime.h>
#include <math.h>
#include <stdint.h>

#define MTOK 50176
#define CCH 384
#define HWN 3136
#define PI_F 3.14159265358979323846f

// ---------------- scratch ----------------
__device__ float g_xt[(size_t)MTOK * CCH];
__device__ float g_xg[(size_t)MTOK * CCH];
__device__ float g_z [(size_t)MTOK * CCH];
__device__ float g_t1[(size_t)MTOK * CCH];
__device__ float g_u0[(size_t)MTOK * CCH];
__device__ float g_v0[(size_t)MTOK * CCH];
__device__ float g_cosb[(size_t)HWN * CCH];
__device__ float g_sinb[(size_t)HWN * CCH];
__device__ float g_D[56 * 56];
__device__ float g_wl[768 * 384];
__device__ float g_wv[384 * 384];
__device__ float g_wo[384 * 384];

__device__ __forceinline__ unsigned f2tf32(float x) {
    unsigned r;
    asm("cvt.rna.tf32.f32 %0, %1;" : "=r"(r) : "f"(x));
    return r;
}
__device__ __forceinline__ float round_tf32(float x) {
    return __uint_as_float(f2tf32(x));
}
__device__ __forceinline__ uint32_t smem_u32(const void* p) {
    uint32_t a;
    asm("{ .reg .u64 t; cvta.to.shared.u64 t, %1; cvt.u32.u64 %0, t; }" : "=r"(a) : "l"(p));
    return a;
}
#define CP16(smaddr, gptr) \
    asm volatile("cp.async.ca.shared.global [%0], [%1], 16;" :: "r"(smaddr), "l"(gptr))

// ---------------- weight pre-round ----------------
__global__ void cvtw_k(const float* __restrict__ in, float* __restrict__ out, int n) {
    int i = blockIdx.x * 256 + threadIdx.x;
    if (i < n) out[i] = round_tf32(in[i]);
}

// ---------------- DCT matrix init ----------------
__global__ void dct_init_k(float* D) {
    int idx = blockIdx.x * 256 + threadIdx.x;
    if (idx < 56 * 56) {
        int k = idx / 56, n = idx % 56;
        double v = cos(3.14159265358979323846 * (2.0 * n + 1.0) * k / 112.0) * sqrt(2.0 / 56.0);
        if (k == 0) v *= (1.0 / sqrt(2.0));
        D[idx] = (float)v;
    }
}

// ---------------- depthwise 3x3 conv -> token-major (tf32-rounded output) ----------------
__global__ void dwconv_k(const float* __restrict__ x, const float* __restrict__ w,
                         const float* __restrict__ bias, float* __restrict__ xt) {
    __shared__ float s[8][33];
    int tx = threadIdx.x, ty = threadIdx.y;
    int wseg = blockIdx.x & 1;
    int h = blockIdx.x >> 1;
    int c = blockIdx.y * 8 + ty;
    int b = blockIdx.z;
    int ww = wseg * 32 + tx;

    if (ww < 56) {
        float acc = bias[c];
        const float* xp = x + ((size_t)(b * CCH + c) * 56) * 56;
        const float* wp = w + c * 9;
        #pragma unroll
        for (int kh = 0; kh < 3; kh++) {
            int hh = h + kh - 1;
            if (hh < 0 || hh >= 56) continue;
            #pragma unroll
            for (int kw = 0; kw < 3; kw++) {
                int wc = ww + kw - 1;
                if (wc < 0 || wc >= 56) continue;
                acc += xp[hh * 56 + wc] * wp[kh * 3 + kw];
            }
        }
        s[ty][tx] = acc;
    }
    __syncthreads();
    int tid = ty * 32 + tx;
    int wi = tid >> 3, ci = tid & 7;
    int wo = wseg * 32 + wi;
    if (wo < 56) {
        int cout = blockIdx.y * 8 + ci;
        size_t tok = (size_t)b * HWN + h * 56 + wo;
        xt[tok * CCH + cout] = round_tf32(s[ci][wi]);
    }
}

// ---------------- TF32 TC GEMM: 8 warps x (64x32), cp.async 3-stage ----------------
#define TBM 128
#define TBN 128
#define TBK 16
#define NST 3

template <int EPI>
__global__ void __launch_bounds__(256, 2) gemm_tc(
    const float* __restrict__ A, const float* __restrict__ Wt,
    const float* __restrict__ bias,
    float* __restrict__ O0, float* __restrict__ O1,
    const float* __restrict__ U, const float* __restrict__ cosb,
    const float* __restrict__ sinb, const float* __restrict__ velb,
    const float* __restrict__ alphap,
    int M, int N, int K) {
    __shared__ unsigned As[NST][TBM][TBK];
    __shared__ unsigned Bs[NST][TBN][TBK];

    int tid = threadIdx.x;
    int lane = tid & 31;
    int warp = tid >> 5;
    int wm = warp & 1;
    int wn = warp >> 1;
    int m0 = blockIdx.y * TBM;
    int n0 = blockIdx.x * TBN;
    int grp = lane >> 2;
    int qd = lane & 3;

    float acc[4][4][4];
    #pragma unroll
    for (int i = 0; i < 4; i++)
        #pragma unroll
        for (int j = 0; j < 4; j++)
            #pragma unroll
            for (int r = 0; r < 4; r++) acc[i][j][r] = 0.f;

    int row0 = tid >> 2;
    int seg  = tid & 3;
    const float* ga0 = A + (size_t)(m0 + row0) * K + seg * 4;
    const float* ga1 = A + (size_t)(m0 + row0 + 64) * K + seg * 4;
    const float* gb0 = Wt + (size_t)(n0 + row0) * K + seg * 4;
    const float* gb1 = Wt + (size_t)(n0 + row0 + 64) * K + seg * 4;
    uint32_t asb = smem_u32(&As[0][0][0]) + row0 * 64 + seg * 16;
    uint32_t bsb = smem_u32(&Bs[0][0][0]) + row0 * 64 + seg * 16;

    int stages = K / TBK;

    #pragma unroll
    for (int p = 0; p < 2; p++) {
        int k0 = p * TBK;
        uint32_t sa = asb + p * 8192;
        uint32_t sbm = bsb + p * 8192;
        CP16(sa, ga0 + k0);
        CP16(sa + 64 * 64, ga1 + k0);
        CP16(sbm, gb0 + k0);
        CP16(sbm + 64 * 64, gb1 + k0);
        asm volatile("cp.async.commit_group;");
    }

    for (int it = 0; it < stages; it++) {
        if (it + 2 < stages) {
            asm volatile("cp.async.wait_group 1;");
        } else {
            asm volatile("cp.async.wait_group 0;");
        }
        __syncthreads();
        if (it + 2 < stages) {
            int s = (it + 2) % NST;
            int k0 = (it + 2) * TBK;
            uint32_t sa = asb + s * 8192;
            uint32_t sbm = bsb + s * 8192;
            CP16(sa, ga0 + k0);
            CP16(sa + 64 * 64, ga1 + k0);
            CP16(sbm, gb0 + k0);
            CP16(sbm + 64 * 64, gb1 + k0);
            asm volatile("cp.async.commit_group;");
        }

        int s = it % NST;
        uint4 alo[4], ahi[4];
        #pragma unroll
        for (int mt = 0; mt < 4; mt++) {
            int mb = wm * 64 + mt * 16;
            alo[mt] = *(const uint4*)&As[s][mb + grp][qd * 4];
            ahi[mt] = *(const uint4*)&As[s][mb + grp + 8][qd * 4];
        }
        #pragma unroll
        for (int nt = 0; nt < 4; nt++) {
            int nb = wn * 32 + nt * 8;
            uint4 bv = *(const uint4*)&Bs[s][nb + grp][qd * 4];
            #pragma unroll
            for (int mt = 0; mt < 4; mt++) {
                asm volatile(
                    "mma.sync.aligned.m16n8k8.row.col.f32.tf32.tf32.f32 "
                    "{%0,%1,%2,%3}, {%4,%5,%6,%7}, {%8,%9}, {%0,%1,%2,%3};"
                    : "+f"(acc[mt][nt][0]), "+f"(acc[mt][nt][1]),
                      "+f"(acc[mt][nt][2]), "+f"(acc[mt][nt][3])
                    : "r"(alo[mt].x), "r"(ahi[mt].x), "r"(alo[mt].y), "r"(ahi[mt].y),
                      "r"(bv.x), "r"(bv.y));
                asm volatile(
                    "mma.sync.aligned.m16n8k8.row.col.f32.tf32.tf32.f32 "
                    "{%0,%1,%2,%3}, {%4,%5,%6,%7}, {%8,%9}, {%0,%1,%2,%3};"
                    : "+f"(acc[mt][nt][0]), "+f"(acc[mt][nt][1]),
                      "+f"(acc[mt][nt][2]), "+f"(acc[mt][nt][3])
                    : "r"(alo[mt].z), "r"(ahi[mt].z), "r"(alo[mt].w), "r"(ahi[mt].w),
                      "r"(bv.z), "r"(bv.w));
            }
        }
        __syncthreads();
    }

    float al = 0.f;
    if (EPI == 2) al = alphap[0];

    #pragma unroll
    for (int mt = 0; mt < 4; mt++) {
        int row0e = m0 + wm * 64 + mt * 16 + grp;
        #pragma unroll
        for (int nt = 0; nt < 4; nt++) {
            int col = n0 + wn * 32 + nt * 8 + qd * 2;
            float b0 = 0.f, b1 = 0.f;
            if (EPI == 0 || EPI == 1) { b0 = bias[col]; b1 = bias[col + 1]; }
            #pragma unroll
            for (int half = 0; half < 2; half++) {
                int row = row0e + half * 8;
                float v0 = acc[mt][nt][half * 2 + 0] + b0;
                float v1 = acc[mt][nt][half * 2 + 1] + b1;
                if (EPI == 0) {
                    if (col < 384)
                        *(float2*)&O0[(size_t)row * 384 + col] = make_float2(v0, v1);
                    else
                        *(float2*)&O1[(size_t)row * 384 + (col - 384)] = make_float2(v0, v1);
                } else if (EPI == 1) {
                    *(float2*)&O0[(size_t)row * N + col] = make_float2(v0, v1);
                } else {
                    int ij = row % HWN;
                    int i = ij / 56, j = ij % 56;
                    float wnv = PI_F * i / 56.f, wmv = PI_F * j / 56.f;
                    float decay = expf(-(wnv * wnv + wmv * wmv));
                    float2 uv = *(const float2*)&U[(size_t)row * 384 + col];
                    float ua = uv.x * decay, ub = uv.y * decay;
                    float va = v0, vb = v1;
                    if (ij == 0) { va += 56.f * velb[col]; vb += 56.f * velb[col + 1]; }
                    va *= decay; vb *= decay;
                    float2 cv = *(const float2*)&cosb[(size_t)ij * 384 + col];
                    float2 sv = *(const float2*)&sinb[(size_t)ij * 384 + col];
                    float fa = cv.x * ua + sv.x * (va + 0.5f * al * ua);
                    float fb = cv.y * ub + sv.y * (vb + 0.5f * al * ub);
                    *(float2*)&O0[(size_t)row * 384 + col] = make_float2(fa, fb);
                }
            }
        }
    }
}

// ---------------- fp32 FFMA GEMM for cos/sin table ----------------
#define BM 128
#define BN 64
#define BK 16

__global__ void __launch_bounds__(256) gemm_cs(
    const float* __restrict__ A, const float* __restrict__ Wt,
    const float* __restrict__ bias, const float* __restrict__ cptr,
    float* __restrict__ O0, float* __restrict__ O1,
    int M, int N, int K) {
    __shared__ float As[BK][BM + 4];
    __shared__ float Ws[BK][BN + 4];
    int tid = threadIdx.x;
    int m0 = blockIdx.y * BM;
    int n0 = blockIdx.x * BN;
    int mt = tid >> 4;
    int nt = tid & 15;

    float acc[8][4];
    #pragma unroll
    for (int i = 0; i < 8; i++)
        #pragma unroll
        for (int j = 0; j < 4; j++) acc[i][j] = 0.f;

    for (int k0 = 0; k0 < K; k0 += BK) {
        #pragma unroll
        for (int u = 0; u < 2; u++) {
            int f = tid + u * 256;
            int r = f >> 2, cq = f & 3;
            float4 v = make_float4(0.f, 0.f, 0.f, 0.f);
            if (m0 + r < M)
                v = *(const float4*)(A + (size_t)(m0 + r) * K + k0 + cq * 4);
            As[cq * 4 + 0][r] = v.x; As[cq * 4 + 1][r] = v.y;
            As[cq * 4 + 2][r] = v.z; As[cq * 4 + 3][r] = v.w;
        }
        {
            int r = tid >> 2, cq = tid & 3;
            float4 v = *(const float4*)(Wt + (size_t)(n0 + r) * K + k0 + cq * 4);
            Ws[cq * 4 + 0][r] = v.x; Ws[cq * 4 + 1][r] = v.y;
            Ws[cq * 4 + 2][r] = v.z; Ws[cq * 4 + 3][r] = v.w;
        }
        __syncthreads();
        #pragma unroll
        for (int kk = 0; kk < BK; kk++) {
            float4 a0 = *(const float4*)&As[kk][mt * 8];
            float4 a1 = *(const float4*)&As[kk][mt * 8 + 4];
            float4 bv = *(const float4*)&Ws[kk][nt * 4];
            float av[8] = {a0.x, a0.y, a0.z, a0.w, a1.x, a1.y, a1.z, a1.w};
            float bvv[4] = {bv.x, bv.y, bv.z, bv.w};
            #pragma unroll
            for (int i = 0; i < 8; i++)
                #pragma unroll
                for (int j = 0; j < 4; j++) acc[i][j] += av[i] * bvv[j];
        }
        __syncthreads();
    }

    float cc = cptr[0], ic = 1.f / (cc + 1e-6f);

    #pragma unroll
    for (int i = 0; i < 8; i++) {
        int m = m0 + mt * 8 + i;
        if (m >= M) continue;
        #pragma unroll
        for (int j = 0; j < 4; j++) {
            int n = n0 + nt * 4 + j;
            float v = acc[i][j] + bias[n];
            v = fmaxf(v, 0.f);
            float a = cc * v;
            O0[(size_t)m * N + n] = cosf(a);
            O1[(size_t)m * N + n] = sinf(a) * ic;
        }
    }
}

// ---------------- tensor-core batched DCT stage ----------------
// O[g][i,n] = sum_h Deff[i,h] X[g][h,n], Deff = D or D^T, 56x56, N-tile 128.
// A = Deff padded to 64x64 in smem (pitch 60), B = X tile [k=h][n] (pitch 136).
// ROUND=1 rounds the output to tf32 (when it feeds a TC GEMM).
template <int ROUND>
__global__ void __launch_bounds__(256) dct_tc(const float* __restrict__ Dm, int transD,
                                              const float* __restrict__ X,
                                              float* __restrict__ O, int N) {
    __shared__ float Ds[64][60];
    __shared__ float Xs[56][136];
    int tid = threadIdx.x;
    int g = blockIdx.y;
    int n0 = blockIdx.x * 128;

    for (int f = tid; f < 64 * 60; f += 256) {
        int i = f / 60, k = f - i * 60;
        float v = 0.f;
        if (i < 56 && k < 56)
            v = round_tf32(transD ? Dm[k * 56 + i] : Dm[i * 56 + k]);
        Ds[i][k] = v;
    }
    const float* Xg = X + (size_t)g * 56 * N + n0;
    for (int f = tid; f < 56 * 32; f += 256) {
        int h = f >> 5, n4 = (f & 31) * 4;
        float4 v = *(const float4*)(Xg + (size_t)h * N + n4);
        Xs[h][n4 + 0] = round_tf32(v.x);
        Xs[h][n4 + 1] = round_tf32(v.y);
        Xs[h][n4 + 2] = round_tf32(v.z);
        Xs[h][n4 + 3] = round_tf32(v.w);
    }
    __syncthreads();

    int warp = tid >> 5, lane = tid & 31;
    int grp = lane >> 2, qd = lane & 3;
    int nb = warp * 16;

    float acc[4][2][4];
    #pragma unroll
    for (int mt = 0; mt < 4; mt++)
        #pragma unroll
        for (int nt = 0; nt < 2; nt++)
            #pragma unroll
            for (int r = 0; r < 4; r++) acc[mt][nt][r] = 0.f;

    #pragma unroll
    for (int kc = 0; kc < 7; kc++) {
        int k0 = kc * 8;
        unsigned a[4][4];
        #pragma unroll
        for (int mt = 0; mt < 4; mt++) {
            int mrow = mt * 16 + grp;
            a[mt][0] = __float_as_uint(Ds[mrow][k0 + qd]);
            a[mt][1] = __float_as_uint(Ds[mrow + 8][k0 + qd]);
            a[mt][2] = __float_as_uint(Ds[mrow][k0 + qd + 4]);
            a[mt][3] = __float_as_uint(Ds[mrow + 8][k0 + qd + 4]);
        }
        #pragma unroll
        for (int nt = 0; nt < 2; nt++) {
            unsigned b0 = __float_as_uint(Xs[k0 + qd][nb + nt * 8 + grp]);
            unsigned b1 = __float_as_uint(Xs[k0 + qd + 4][nb + nt * 8 + grp]);
            #pragma unroll
            for (int mt = 0; mt < 4; mt++) {
                asm volatile(
                    "mma.sync.aligned.m16n8k8.row.col.f32.tf32.tf32.f32 "
                    "{%0,%1,%2,%3}, {%4,%5,%6,%7}, {%8,%9}, {%0,%1,%2,%3};"
                    : "+f"(acc[mt][nt][0]), "+f"(acc[mt][nt][1]),
                      "+f"(acc[mt][nt][2]), "+f"(acc[mt][nt][3])
                    : "r"(a[mt][0]), "r"(a[mt][1]), "r"(a[mt][2]), "r"(a[mt][3]),
                      "r"(b0), "r"(b1));
            }
        }
    }

    float* Og = O + (size_t)g * 56 * N + n0;
    #pragma unroll
    for (int mt = 0; mt < 4; mt++) {
        #pragma unroll
        for (int half = 0; half < 2; half++) {
            int i = mt * 16 + grp + half * 8;
            if (i >= 56) continue;
            #pragma unroll
            for (int nt = 0; nt < 2; nt++) {
                int col = nb + nt * 8 + qd * 2;
                float v0 = acc[mt][nt][half * 2 + 0];
                float v1 = acc[mt][nt][half * 2 + 1];
                if (ROUND) { v0 = round_tf32(v0); v1 = round_tf32(v1); }
                *(float2*)&Og[(size_t)i * N + col] = make_float2(v0, v1);
            }
        }
    }
}

// ---------------- LayerNorm + SiLU gate (tf32-rounded output) ----------------
__global__ void ln_gate_k(const float* __restrict__ y, const float* __restrict__ z,
                          const float* __restrict__ g, const float* __restrict__ b,
                          float* __restrict__ out) {
    int warp = threadIdx.x >> 5, lane = threadIdx.x & 31;
    size_t m = (size_t)blockIdx.x * 8 + warp;
    const float* yr = y + m * CCH;
    float vals[12];
    float s = 0.f;
    #pragma unroll
    for (int t = 0; t < 12; t++) { vals[t] = yr[lane + t * 32]; s += vals[t]; }
    #pragma unroll
    for (int o = 16; o > 0; o >>= 1) s += __shfl_xor_sync(0xffffffff, s, o);
    float mu = s * (1.f / 384.f);
    float q = 0.f;
    #pragma unroll
    for (int t = 0; t < 12; t++) { float d = vals[t] - mu; q += d * d; }
    #pragma unroll
    for (int o = 16; o > 0; o >>= 1) q += __shfl_xor_sync(0xffffffff, q, o);
    float rstd = rsqrtf(q * (1.f / 384.f) + 1e-5f);
    #pragma unroll
    for (int t = 0; t < 12; t++) {
        int c = lane + t * 32;
        float yn = (vals[t] - mu) * rstd * g[c] + b[c];
        float zz = z[m * CCH + c];
        out[m * CCH + c] = round_tf32(yn * (zz / (1.f + expf(-zz))));
    }
}

// ---------------- [B,HW,C] -> [B,C,HW] transpose ----------------
__global__ void transpose_k(const float* __restrict__ in, float* __restrict__ out) {
    __shared__ float s[32][33];
    int tx = threadIdx.x, ty = threadIdx.y;
    int hw0 = blockIdx.x * 32;
    int c0 = blockIdx.y * 32;
    int b = blockIdx.z;
    #pragma unroll
    for (int r = 0; r < 4; r++) {
        int hw = hw0 + ty + r * 8;
        s[ty + r * 8][tx] = in[((size_t)b * HWN + hw) * CCH + c0 + tx];
    }
    __syncthreads();
    #pragma unroll
    for (int r = 0; r < 4; r++) {
        int c = c0 + ty + r * 8;
        out[((size_t)b * CCH + c) * HWN + hw0 + tx] = s[tx][ty + r * 8];
    }
}

// ---------------- launch ----------------
extern "C" void kernel_launch(void* const* d_in, const int* in_sizes, int n_in,
                              void* d_out, int out_size) {
    const float* x          = (const float*)d_in[0];
    const float* freq_embed = (const float*)d_in[1];
    const float* dw_w       = (const float*)d_in[2];
    const float* dw_b       = (const float*)d_in[3];
    const float* lin_w      = (const float*)d_in[4];
    const float* lin_b      = (const float*)d_in[5];
    const float* vel_w      = (const float*)d_in[6];
    const float* vel_b      = (const float*)d_in[7];
    const float* tok_w      = (const float*)d_in[8];
    const float* tok_b      = (const float*)d_in[9];
    const float* ln_g       = (const float*)d_in[10];
    const float* ln_b       = (const float*)d_in[11];
    const float* out_w      = (const float*)d_in[12];
    const float* out_b      = (const float*)d_in[13];
    const float* cptr       = (const float*)d_in[14];
    const float* alphap     = (const float*)d_in[15];
    float* outp = (float*)d_out;

    float *xt, *xg, *z, *t1, *u0, *v0, *cb, *sb, *Dm, *wl, *wv, *wo;
    cudaGetSymbolAddress((void**)&xt, g_xt);
    cudaGetSymbolAddress((void**)&xg, g_xg);
    cudaGetSymbolAddress((void**)&z,  g_z);
    cudaGetSymbolAddress((void**)&t1, g_t1);
    cudaGetSymbolAddress((void**)&u0, g_u0);
    cudaGetSymbolAddress((void**)&v0, g_v0);
    cudaGetSymbolAddress((void**)&cb, g_cosb);
    cudaGetSymbolAddress((void**)&sb, g_sinb);
    cudaGetSymbolAddress((void**)&Dm, g_D);
    cudaGetSymbolAddress((void**)&wl, g_wl);
    cudaGetSymbolAddress((void**)&wv, g_wv);
    cudaGetSymbolAddress((void**)&wo, g_wo);

    dct_init_k<<<13, 256>>>(Dm);
    cvtw_k<<<(768 * 384 + 255) / 256, 256>>>(lin_w, wl, 768 * 384);
    cvtw_k<<<(384 * 384 + 255) / 256, 256>>>(vel_w, wv, 384 * 384);
    cvtw_k<<<(384 * 384 + 255) / 256, 256>>>(out_w, wo, 384 * 384);

    // depthwise conv -> token-major xt (tf32-rounded)
    dwconv_k<<<dim3(112, 48, 16), dim3(32, 8)>>>(x, dw_w, dw_b, xt);

    // cos/sin tables (fp32 for precision)
    gemm_cs<<<dim3(384 / BN, (HWN + BM - 1) / BM), 256>>>(freq_embed, tok_w, tok_b, cptr,
                                                          cb, sb, HWN, 384, 384);

    // xz = xt @ lin_w.T + lin_b ; split -> xg, z
    gemm_tc<0><<<dim3(768 / TBN, MTOK / TBM), 256>>>(xt, wl, lin_b, xg, z,
                                                     nullptr, nullptr, nullptr, nullptr, nullptr,
                                                     MTOK, 768, 384);

    // u0 = DCT2(xg): TC stages; stage2 output rounded (feeds gemm<2>)
    dct_tc<0><<<dim3(168, 16), 256>>>(Dm, 0, xg, t1, 21504);
    dct_tc<1><<<dim3(3, 896), 256>>>(Dm, 0, t1, u0, 384);

    // fin = mod(u0, u0 @ vel_w.T) -> t1   (mod fused into epilogue)
    gemm_tc<2><<<dim3(384 / TBN, MTOK / TBM), 256>>>(u0, wv, nullptr, t1, nullptr,
                                                     u0, cb, sb, vel_b, alphap,
                                                     MTOK, 384, 384);

    // y = IDCT2(fin) -> u0  (TC stages, fp32 outputs)
    dct_tc<0><<<dim3(168, 16), 256>>>(Dm, 1, t1, xg, 21504);
    dct_tc<0><<<dim3(3, 896), 256>>>(Dm, 1, xg, u0, 384);

    // LayerNorm + SiLU(z) gate -> v0 (tf32-rounded)
    ln_gate_k<<<MTOK / 8, 256>>>(u0, z, ln_g, ln_b, v0);

    // out = gated @ out_w.T + out_b -> t1, then transpose to NCHW
    gemm_tc<1><<<dim3(384 / TBN, MTOK / TBM), 256>>>(v0, wo, out_b, t1, nullptr,
                                                     nullptr, nullptr, nullptr, nullptr, nullptr,
                                                     MTOK, 384, 384);
    transpose_k<<<dim3(98, 12, 16), dim3(32, 8)>>>(t1, outp);
}